// round 15
// baseline (speedup 1.0000x reference)
#include <cuda_runtime.h>
#include <cstdint>

// ---------------- static scratch (no allocations allowed) ----------------
#define N_MAX 100000
#define E_MAX 1600000

__device__ float g_h  [(size_t)N_MAX * 128];   // post-GEMM features
__device__ float g_y  [(size_t)N_MAX * 128];   // layer outputs (ping-pong)
__device__ float g_as [N_MAX * 8];
__device__ float g_ad [N_MAX * 8];
__device__ float g_h3 [N_MAX * 6];
__device__ float g_as3[N_MAX];
__device__ float g_ad3[N_MAX];
__device__ int   g_deg   [N_MAX];
__device__ int   g_incl  [N_MAX];
__device__ int   g_rowptr[N_MAX + 1];
__device__ int   g_wofs  [N_MAX];
__device__ int   g_srcs  [E_MAX + N_MAX];      // dst-sorted source ids (CSR payload)
__device__ int   g_esrc  [E_MAX];
__device__ int   g_edst  [E_MAX];
__device__ int   g_bsums [128];
__device__ int   g_flag;                       // 1 => edge_index stored as int64

// ---------------- edge dtype detection + conversion ----------------
// int64 little-endian with values in [0, 2^31): every odd int32 word is 0.
__global__ void k_detect(const int* __restrict__ ei) {
    __shared__ int any;
    if (threadIdx.x == 0) any = 0;
    __syncthreads();
    for (int i = threadIdx.x; i < 2048; i += blockDim.x)
        if (ei[2 * i + 1] != 0) any = 1;
    __syncthreads();
    if (threadIdx.x == 0) g_flag = (any == 0) ? 1 : 0;
}

__global__ void k_convert(const void* __restrict__ ei, int E) {
    int i = blockIdx.x * blockDim.x + threadIdx.x;
    if (i >= E) return;
    if (g_flag) {
        const long long* p = (const long long*)ei;
        g_esrc[i] = (int)p[i];
        g_edst[i] = (int)p[(size_t)E + i];
    } else {
        const int* p = (const int*)ei;
        g_esrc[i] = p[i];
        g_edst[i] = p[E + i];
    }
}

// ---------------- CSR-by-dst build ----------------
__global__ void k_initdeg(int n) {
    int i = blockIdx.x * blockDim.x + threadIdx.x;
    if (i < n) g_deg[i] = 1;   // self-loop
}
__global__ void k_count(int E) {
    int i = blockIdx.x * blockDim.x + threadIdx.x;
    if (i < E) atomicAdd(&g_deg[g_edst[i]], 1);
}
__global__ void k_scan1(int n) {
    __shared__ int sh[1024];
    int i = blockIdx.x * 1024 + threadIdx.x;
    int v = (i < n) ? g_deg[i] : 0;
    sh[threadIdx.x] = v;
    __syncthreads();
    for (int off = 1; off < 1024; off <<= 1) {
        int t = (threadIdx.x >= off) ? sh[threadIdx.x - off] : 0;
        __syncthreads();
        sh[threadIdx.x] += t;
        __syncthreads();
    }
    if (i < n) g_incl[i] = sh[threadIdx.x];
    if (threadIdx.x == 1023) g_bsums[blockIdx.x] = sh[1023];
}
__global__ void k_scan2(int nb) {
    __shared__ int sh[128];
    int t = threadIdx.x;
    int v = (t < nb) ? g_bsums[t] : 0;
    sh[t] = v;
    __syncthreads();
    for (int off = 1; off < 128; off <<= 1) {
        int u = (t >= off) ? sh[t - off] : 0;
        __syncthreads();
        sh[t] += u;
        __syncthreads();
    }
    if (t < nb) g_bsums[t] = sh[t] - v;   // exclusive
}
__global__ void k_scan3(int n) {
    int i = blockIdx.x * 1024 + threadIdx.x;
    if (i < n) {
        int b = g_bsums[i >> 10];
        g_rowptr[i] = g_incl[i] - g_deg[i] + b;
        if (i == n - 1) g_rowptr[n] = g_incl[i] + b;
    }
}
__global__ void k_self(int n) {
    int i = blockIdx.x * blockDim.x + threadIdx.x;
    if (i < n) {
        int r = g_rowptr[i];
        g_srcs[r] = i;          // self-loop first (deterministic slot)
        g_wofs[i] = r + 1;
    }
}
__global__ void k_scatter(int E) {
    int i = blockIdx.x * blockDim.x + threadIdx.x;
    if (i < E) {
        int d = g_edst[i];
        int pos = atomicAdd(&g_wofs[d], 1);
        g_srcs[pos] = g_esrc[i];
    }
}

// ---------------- SGEMM: [M,KDIM] x [KDIM,128] -> g_h [M,128] ----------------
template <int KDIM, bool A_GY>
__global__ __launch_bounds__(256) void k_sgemm(const float* __restrict__ Aext,
                                               const float* __restrict__ B, int M) {
    const float* A = A_GY ? (const float*)g_y : Aext;
    __shared__ float As[16][129];   // padded: conflict-free transposed stores
    __shared__ float Bs[16][128];
    const int tid = threadIdx.x;
    const int tx = tid & 15, ty = tid >> 4;
    const int rowBase = blockIdx.x * 128;
    float acc[8][8];
#pragma unroll
    for (int i = 0; i < 8; i++)
#pragma unroll
        for (int j = 0; j < 8; j++) acc[i][j] = 0.f;

    for (int k0 = 0; k0 < KDIM; k0 += 16) {
#pragma unroll
        for (int i = 0; i < 2; i++) {
            int idx = tid + i * 256;
            int r = idx >> 2, kq = idx & 3;
            int row = rowBase + r;
            float4 v = make_float4(0.f, 0.f, 0.f, 0.f);
            if (row < M) v = *(const float4*)(A + (size_t)row * KDIM + k0 + kq * 4);
            As[kq * 4 + 0][r] = v.x; As[kq * 4 + 1][r] = v.y;
            As[kq * 4 + 2][r] = v.z; As[kq * 4 + 3][r] = v.w;
        }
#pragma unroll
        for (int i = 0; i < 2; i++) {
            int idx = tid + i * 256;
            int kr = idx >> 5, nq = idx & 31;
            *(float4*)(&Bs[kr][nq * 4]) = *(const float4*)(B + (size_t)(k0 + kr) * 128 + nq * 4);
        }
        __syncthreads();
#pragma unroll
        for (int kk = 0; kk < 16; kk++) {
            float a[8];
#pragma unroll
            for (int i = 0; i < 8; i++) a[i] = As[kk][ty * 8 + i];
            float4 b0 = *(const float4*)(&Bs[kk][tx * 4]);
            float4 b1 = *(const float4*)(&Bs[kk][64 + tx * 4]);
            float bb[8] = {b0.x, b0.y, b0.z, b0.w, b1.x, b1.y, b1.z, b1.w};
#pragma unroll
            for (int i = 0; i < 8; i++)
#pragma unroll
                for (int j = 0; j < 8; j++) acc[i][j] += a[i] * bb[j];
        }
        __syncthreads();
    }
#pragma unroll
    for (int i = 0; i < 8; i++) {
        int row = rowBase + ty * 8 + i;
        if (row < M) {
            float4 o0 = make_float4(acc[i][0], acc[i][1], acc[i][2], acc[i][3]);
            float4 o1 = make_float4(acc[i][4], acc[i][5], acc[i][6], acc[i][7]);
            *(float4*)(g_h + (size_t)row * 128 + tx * 4) = o0;
            *(float4*)(g_h + (size_t)row * 128 + 64 + tx * 4) = o1;
        }
    }
}

// ---------------- attention coefficients: a_s/a_d per node (layers 1,2) ----------------
__global__ void k_coef(const float* __restrict__ attS, const float* __restrict__ attD, int N) {
    int gw = (blockIdx.x * blockDim.x + threadIdx.x) >> 5;
    int lane = threadIdx.x & 31;
    if (gw >= N) return;
    float4 hv = *(const float4*)(g_h + (size_t)gw * 128 + lane * 4);
    float4 sv = *(const float4*)(attS + lane * 4);   // att flattened [H*D]=[128]
    float4 dv = *(const float4*)(attD + lane * 4);
    float ps = hv.x * sv.x + hv.y * sv.y + hv.z * sv.z + hv.w * sv.w;
    float pd = hv.x * dv.x + hv.y * dv.y + hv.z * dv.z + hv.w * dv.w;
    ps += __shfl_xor_sync(0xffffffffu, ps, 1);
    ps += __shfl_xor_sync(0xffffffffu, ps, 2);
    pd += __shfl_xor_sync(0xffffffffu, pd, 1);
    pd += __shfl_xor_sync(0xffffffffu, pd, 2);
    if ((lane & 3) == 0) {
        g_as[gw * 8 + (lane >> 2)] = ps;
        g_ad[gw * 8 + (lane >> 2)] = pd;
    }
}

// ---------------- softmax + aggregation (layers 1,2): warp per node ----------------
__global__ void k_agg(const float* __restrict__ bias, int N, int do_elu) {
    int gw = (blockIdx.x * blockDim.x + threadIdx.x) >> 5;
    int lane = threadIdx.x & 31;
    if (gw >= N) return;
    const int start = g_rowptr[gw], end = g_rowptr[gw + 1];
    const int hidx = lane >> 2;
    float adv = (lane < 8) ? g_ad[gw * 8 + lane] : 0.f;
    float mx = -3e38f, den = 0.f;
    if (lane < 8) {
        for (int k = start; k < end; k++) {
            int s = g_srcs[k];
            float e = g_as[s * 8 + lane] + adv;
            e = e > 0.f ? e : 0.2f * e;
            mx = fmaxf(mx, e);
        }
        for (int k = start; k < end; k++) {
            int s = g_srcs[k];
            float e = g_as[s * 8 + lane] + adv;
            e = e > 0.f ? e : 0.2f * e;
            den += __expf(e - mx);
        }
    }
    float mxb  = __shfl_sync(0xffffffffu, mx, hidx);
    float rden = 1.f / (__shfl_sync(0xffffffffu, den, hidx) + 1e-16f);
    float advb = __shfl_sync(0xffffffffu, adv, hidx);

    float4 acc = make_float4(0.f, 0.f, 0.f, 0.f);
    for (int k = start; k < end; k++) {
        int s = g_srcs[k];
        float e = g_as[s * 8 + hidx] + advb;
        e = e > 0.f ? e : 0.2f * e;
        float al = __expf(e - mxb) * rden;
        float4 hv = *(const float4*)(g_h + (size_t)s * 128 + lane * 4);
        acc.x += al * hv.x; acc.y += al * hv.y;
        acc.z += al * hv.z; acc.w += al * hv.w;
    }
    float4 bv = *(const float4*)(bias + lane * 4);
    acc.x += bv.x; acc.y += bv.y; acc.z += bv.z; acc.w += bv.w;
    if (do_elu) {
        acc.x = acc.x > 0.f ? acc.x : __expf(acc.x) - 1.f;
        acc.y = acc.y > 0.f ? acc.y : __expf(acc.y) - 1.f;
        acc.z = acc.z > 0.f ? acc.z : __expf(acc.z) - 1.f;
        acc.w = acc.w > 0.f ? acc.w : __expf(acc.w) - 1.f;
    }
    *(float4*)(g_y + (size_t)gw * 128 + lane * 4) = acc;
}

// ---------------- layer 3 GEMM ([N,128]x[128,6]) + coefficients, warp per node ----------------
__global__ void k_gemm3(const float* __restrict__ W3, const float* __restrict__ attS,
                        const float* __restrict__ attD, int N) {
    __shared__ float w[768];
    for (int i = threadIdx.x; i < 768; i += blockDim.x) w[i] = W3[i];
    __syncthreads();
    int gw = (blockIdx.x * blockDim.x + threadIdx.x) >> 5;
    int lane = threadIdx.x & 31;
    if (gw >= N) return;
    float4 xv = *(const float4*)(g_y + (size_t)gw * 128 + lane * 4);
    int c = lane * 4;
    float p[6];
#pragma unroll
    for (int j = 0; j < 6; j++)
        p[j] = xv.x * w[c * 6 + j] + xv.y * w[(c + 1) * 6 + j] +
               xv.z * w[(c + 2) * 6 + j] + xv.w * w[(c + 3) * 6 + j];
#pragma unroll
    for (int j = 0; j < 6; j++)
#pragma unroll
        for (int o = 16; o > 0; o >>= 1) p[j] += __shfl_xor_sync(0xffffffffu, p[j], o);
    if (lane == 0) {
        float s = 0.f, d = 0.f;
#pragma unroll
        for (int j = 0; j < 6; j++) {
            g_h3[(size_t)gw * 6 + j] = p[j];
            s += p[j] * attS[j];
            d += p[j] * attD[j];
        }
        g_as3[gw] = s;
        g_ad3[gw] = d;
    }
}

// ---------------- layer 3 softmax + aggregation, warp per node ----------------
__global__ void k_agg3(const float* __restrict__ b3, float* __restrict__ out, int N) {
    int gw = (blockIdx.x * blockDim.x + threadIdx.x) >> 5;
    int lane = threadIdx.x & 31;
    if (gw >= N) return;
    const int start = g_rowptr[gw], end = g_rowptr[gw + 1];
    const float adv = g_ad3[gw];
    float mx = -3e38f;
    for (int k = start + lane; k < end; k += 32) {
        float e = g_as3[g_srcs[k]] + adv;
        e = e > 0.f ? e : 0.2f * e;
        mx = fmaxf(mx, e);
    }
#pragma unroll
    for (int o = 16; o > 0; o >>= 1) mx = fmaxf(mx, __shfl_xor_sync(0xffffffffu, mx, o));
    float den = 0.f;
    for (int k = start + lane; k < end; k += 32) {
        float e = g_as3[g_srcs[k]] + adv;
        e = e > 0.f ? e : 0.2f * e;
        den += __expf(e - mx);
    }
#pragma unroll
    for (int o = 16; o > 0; o >>= 1) den += __shfl_xor_sync(0xffffffffu, den, o);
    float rden = 1.f / (den + 1e-16f);
    float acc[6] = {0.f, 0.f, 0.f, 0.f, 0.f, 0.f};
    for (int k = start + lane; k < end; k += 32) {
        int s = g_srcs[k];
        float e = g_as3[s] + adv;
        e = e > 0.f ? e : 0.2f * e;
        float al = __expf(e - mx) * rden;
#pragma unroll
        for (int j = 0; j < 6; j++) acc[j] += al * g_h3[(size_t)s * 6 + j];
    }
#pragma unroll
    for (int j = 0; j < 6; j++)
#pragma unroll
        for (int o = 16; o > 0; o >>= 1) acc[j] += __shfl_xor_sync(0xffffffffu, acc[j], o);
    if (lane == 0) {
#pragma unroll
        for (int j = 0; j < 6; j++) out[(size_t)gw * 6 + j] = acc[j] + b3[j];
    }
}

// ---------------- launch ----------------
extern "C" void kernel_launch(void* const* d_in, const int* in_sizes, int n_in,
                              void* d_out, int out_size) {
    const float* x  = (const float*)d_in[0];
    const void*  ei = d_in[1];
    const float* W1 = (const float*)d_in[2];
    const float* b1 = (const float*)d_in[3];
    const float* s1 = (const float*)d_in[4];
    const float* t1 = (const float*)d_in[5];
    const float* W2 = (const float*)d_in[6];
    const float* b2 = (const float*)d_in[7];
    const float* s2 = (const float*)d_in[8];
    const float* t2 = (const float*)d_in[9];
    const float* W3 = (const float*)d_in[10];
    const float* b3 = (const float*)d_in[11];
    const float* s3 = (const float*)d_in[12];
    const float* t3 = (const float*)d_in[13];
    const int N = in_sizes[0] / 256;
    const int E = in_sizes[1] / 2;
    float* out = (float*)d_out;

    const int eb = (E + 255) / 256;
    const int nb = (N + 255) / 256;
    const int sb = (N + 1023) / 1024;
    const int wb = (N * 32 + 255) / 256;   // warp-per-node grids
    const int gb = (N + 127) / 128;

    // graph preprocessing: dst-CSR with deterministic self-loop slot
    k_detect<<<1, 256>>>((const int*)ei);
    k_convert<<<eb, 256>>>(ei, E);
    k_initdeg<<<nb, 256>>>(N);
    k_count<<<eb, 256>>>(E);
    k_scan1<<<sb, 1024>>>(N);
    k_scan2<<<1, 128>>>(sb);
    k_scan3<<<sb, 1024>>>(N);
    k_self<<<nb, 256>>>(N);
    k_scatter<<<eb, 256>>>(E);

    // layer 1: x[ N,256 ] @ W1 -> g_h; attention -> g_y (ELU)
    k_sgemm<256, false><<<gb, 256>>>(x, W1, N);
    k_coef<<<wb, 256>>>(s1, t1, N);
    k_agg<<<wb, 256>>>(b1, N, 1);

    // layer 2: g_y @ W2 -> g_h; attention -> g_y (ELU)
    k_sgemm<128, true><<<gb, 256>>>(x /*unused*/, W2, N);
    k_coef<<<wb, 256>>>(s2, t2, N);
    k_agg<<<wb, 256>>>(b2, N, 1);

    // layer 3: g_y @ W3 -> g_h3 (+coefs); attention -> out (+b3)
    k_gemm3<<<wb, 256>>>(W3, s3, t3, N);
    k_agg3<<<wb, 256>>>(b3, out, N);
}

// round 16
// speedup vs baseline: 1.2111x; 1.2111x over previous
#include <cuda_runtime.h>
#include <cstdint>

// ---------------- static scratch (no allocations allowed) ----------------
#define N_MAX 100000
#define E_MAX 1600000

__device__ float g_h  [(size_t)N_MAX * 128];   // post-GEMM features
__device__ float g_y  [(size_t)N_MAX * 128];   // layer outputs (ping-pong)
__device__ float g_as [N_MAX * 8];
__device__ float g_ad [N_MAX * 8];
__device__ float g_h3 [N_MAX * 6];
__device__ float g_as3[N_MAX];
__device__ float g_ad3[N_MAX];
__device__ int   g_deg   [N_MAX];
__device__ int   g_incl  [N_MAX];
__device__ int   g_rowptr[N_MAX + 1];
__device__ int   g_wofs  [N_MAX];
__device__ int   g_srcs  [E_MAX + N_MAX];      // dst-sorted source ids (CSR payload)
__device__ int   g_esrc  [E_MAX];
__device__ int   g_edst  [E_MAX];
__device__ int   g_bsums [128];
__device__ int   g_flag;                       // 1 => edge_index stored as int64

// ---------------- edge dtype detection ----------------
__global__ void k_detect(const int* __restrict__ ei) {
    __shared__ int any;
    if (threadIdx.x == 0) any = 0;
    __syncthreads();
    for (int i = threadIdx.x; i < 2048; i += blockDim.x)
        if (ei[2 * i + 1] != 0) any = 1;
    __syncthreads();
    if (threadIdx.x == 0) g_flag = (any == 0) ? 1 : 0;
}

__global__ void k_initdeg(int n) {
    int i = blockIdx.x * blockDim.x + threadIdx.x;
    if (i < n) g_deg[i] = 1;   // self-loop
}

// convert + degree-count fused (one edge read)
__global__ void k_convert_count(const void* __restrict__ ei, int E) {
    int i = blockIdx.x * blockDim.x + threadIdx.x;
    if (i >= E) return;
    int s, d;
    if (g_flag) {
        const long long* p = (const long long*)ei;
        s = (int)p[i];
        d = (int)p[(size_t)E + i];
    } else {
        const int* p = (const int*)ei;
        s = p[i];
        d = p[E + i];
    }
    g_esrc[i] = s;
    g_edst[i] = d;
    atomicAdd(&g_deg[d], 1);
}

// ---------------- CSR-by-dst build ----------------
__global__ void k_scan1(int n) {
    __shared__ int sh[1024];
    int i = blockIdx.x * 1024 + threadIdx.x;
    int v = (i < n) ? g_deg[i] : 0;
    sh[threadIdx.x] = v;
    __syncthreads();
    for (int off = 1; off < 1024; off <<= 1) {
        int t = (threadIdx.x >= off) ? sh[threadIdx.x - off] : 0;
        __syncthreads();
        sh[threadIdx.x] += t;
        __syncthreads();
    }
    if (i < n) g_incl[i] = sh[threadIdx.x];
    if (threadIdx.x == 1023) g_bsums[blockIdx.x] = sh[1023];
}
__global__ void k_scan2(int nb) {
    __shared__ int sh[128];
    int t = threadIdx.x;
    int v = (t < nb) ? g_bsums[t] : 0;
    sh[t] = v;
    __syncthreads();
    for (int off = 1; off < 128; off <<= 1) {
        int u = (t >= off) ? sh[t - off] : 0;
        __syncthreads();
        sh[t] += u;
        __syncthreads();
    }
    if (t < nb) g_bsums[t] = sh[t] - v;   // exclusive
}
__global__ void k_scan3(int n) {
    int i = blockIdx.x * 1024 + threadIdx.x;
    if (i < n) {
        int b = g_bsums[i >> 10];
        g_rowptr[i] = g_incl[i] - g_deg[i] + b;
        if (i == n - 1) g_rowptr[n] = g_incl[i] + b;
    }
}
__global__ void k_self(int n) {
    int i = blockIdx.x * blockDim.x + threadIdx.x;
    if (i < n) {
        int r = g_rowptr[i];
        g_srcs[r] = i;          // self-loop first (deterministic slot)
        g_wofs[i] = r + 1;
    }
}
__global__ void k_scatter(int E) {
    int i = blockIdx.x * blockDim.x + threadIdx.x;
    if (i < E) {
        int d = g_edst[i];
        int pos = atomicAdd(&g_wofs[d], 1);
        g_srcs[pos] = g_esrc[i];
    }
}

// ---------------- SGEMM: [M,KDIM] x [KDIM,128] -> g_h [M,128] ----------------
// Fused epilogue: per-node attention coefficients a_s/a_d (8 heads of 16 dims)
template <int KDIM, bool A_GY>
__global__ __launch_bounds__(256) void k_sgemm(const float* __restrict__ Aext,
                                               const float* __restrict__ B, int M,
                                               const float* __restrict__ attS,
                                               const float* __restrict__ attD) {
    const float* A = A_GY ? (const float*)g_y : Aext;
    __shared__ float As[16][129];   // padded: conflict-free transposed stores
    __shared__ float Bs[16][128];
    __shared__ float sS[128], sD[128];
    const int tid = threadIdx.x;
    const int tx = tid & 15, ty = tid >> 4;
    const int rowBase = blockIdx.x * 128;
    if (tid < 128) { sS[tid] = attS[tid]; sD[tid] = attD[tid]; }
    float acc[8][8];
#pragma unroll
    for (int i = 0; i < 8; i++)
#pragma unroll
        for (int j = 0; j < 8; j++) acc[i][j] = 0.f;

    for (int k0 = 0; k0 < KDIM; k0 += 16) {
#pragma unroll
        for (int i = 0; i < 2; i++) {
            int idx = tid + i * 256;
            int r = idx >> 2, kq = idx & 3;
            int row = rowBase + r;
            float4 v = make_float4(0.f, 0.f, 0.f, 0.f);
            if (row < M) v = *(const float4*)(A + (size_t)row * KDIM + k0 + kq * 4);
            As[kq * 4 + 0][r] = v.x; As[kq * 4 + 1][r] = v.y;
            As[kq * 4 + 2][r] = v.z; As[kq * 4 + 3][r] = v.w;
        }
#pragma unroll
        for (int i = 0; i < 2; i++) {
            int idx = tid + i * 256;
            int kr = idx >> 5, nq = idx & 31;
            *(float4*)(&Bs[kr][nq * 4]) = *(const float4*)(B + (size_t)(k0 + kr) * 128 + nq * 4);
        }
        __syncthreads();
#pragma unroll
        for (int kk = 0; kk < 16; kk++) {
            float a[8];
#pragma unroll
            for (int i = 0; i < 8; i++) a[i] = As[kk][ty * 8 + i];
            float4 b0 = *(const float4*)(&Bs[kk][tx * 4]);
            float4 b1 = *(const float4*)(&Bs[kk][64 + tx * 4]);
            float bb[8] = {b0.x, b0.y, b0.z, b0.w, b1.x, b1.y, b1.z, b1.w};
#pragma unroll
            for (int i = 0; i < 8; i++)
#pragma unroll
                for (int j = 0; j < 8; j++) acc[i][j] += a[i] * bb[j];
        }
        __syncthreads();
    }
    // epilogue: store h, and fused attention coefficient dots.
    // Thread covers cols [tx*4, tx*4+4) (head tx>>2) and [64+tx*4, ...) (head 4+(tx>>2)).
    float s0v[4], d0v[4], s1v[4], d1v[4];
#pragma unroll
    for (int j = 0; j < 4; j++) {
        s0v[j] = sS[tx * 4 + j];      d0v[j] = sD[tx * 4 + j];
        s1v[j] = sS[64 + tx * 4 + j]; d1v[j] = sD[64 + tx * 4 + j];
    }
#pragma unroll
    for (int i = 0; i < 8; i++) {
        int row = rowBase + ty * 8 + i;
        float ps0 = 0.f, pd0 = 0.f, ps1 = 0.f, pd1 = 0.f;
#pragma unroll
        for (int j = 0; j < 4; j++) {
            ps0 += acc[i][j] * s0v[j];     pd0 += acc[i][j] * d0v[j];
            ps1 += acc[i][4 + j] * s1v[j]; pd1 += acc[i][4 + j] * d1v[j];
        }
        // reduce over the 4-thread head group (lane bits 0,1 == tx bits 0,1; same ty)
        ps0 += __shfl_xor_sync(0xffffffffu, ps0, 1); ps0 += __shfl_xor_sync(0xffffffffu, ps0, 2);
        pd0 += __shfl_xor_sync(0xffffffffu, pd0, 1); pd0 += __shfl_xor_sync(0xffffffffu, pd0, 2);
        ps1 += __shfl_xor_sync(0xffffffffu, ps1, 1); ps1 += __shfl_xor_sync(0xffffffffu, ps1, 2);
        pd1 += __shfl_xor_sync(0xffffffffu, pd1, 1); pd1 += __shfl_xor_sync(0xffffffffu, pd1, 2);
        if (row < M) {
            float4 o0 = make_float4(acc[i][0], acc[i][1], acc[i][2], acc[i][3]);
            float4 o1 = make_float4(acc[i][4], acc[i][5], acc[i][6], acc[i][7]);
            *(float4*)(g_h + (size_t)row * 128 + tx * 4) = o0;
            *(float4*)(g_h + (size_t)row * 128 + 64 + tx * 4) = o1;
            if ((tx & 3) == 0) {
                int hg = tx >> 2;
                g_as[row * 8 + hg] = ps0;     g_ad[row * 8 + hg] = pd0;
                g_as[row * 8 + 4 + hg] = ps1; g_ad[row * 8 + 4 + hg] = pd1;
            }
        }
    }
}

// ---------------- softmax + aggregation (layers 1,2): warp per node ----------------
// Max-free softmax: alpha = exp(leaky(e)) / sum exp(leaky(e)); |e| is small here.
__global__ void k_agg(const float* __restrict__ bias, int N, int do_elu) {
    int gw = (blockIdx.x * blockDim.x + threadIdx.x) >> 5;
    int lane = threadIdx.x & 31;
    if (gw >= N) return;
    const int start = g_rowptr[gw], end = g_rowptr[gw + 1];

    // pass 1: denominators for all 8 heads, all 32 lanes (4 edges x 8 heads)
    const int h8 = lane & 7;
    const float adv = g_ad[gw * 8 + h8];
    float den = 0.f;
    for (int k = start + (lane >> 3); k < end; k += 4) {
        int s = g_srcs[k];
        float e = g_as[s * 8 + h8] + adv;
        e = e > 0.f ? e : 0.2f * e;
        den += __expf(e);
    }
    den += __shfl_xor_sync(0xffffffffu, den, 8);
    den += __shfl_xor_sync(0xffffffffu, den, 16);

    const int hidx = lane >> 2;          // head for this lane's channel group
    float rden = 1.f / (__shfl_sync(0xffffffffu, den, hidx) + 1e-16f);
    float advb = __shfl_sync(0xffffffffu, adv, hidx);

    // pass 2: weighted aggregation, unrolled x2 to hide L2 latency
    float4 acc = make_float4(0.f, 0.f, 0.f, 0.f);
    int k = start;
    for (; k + 1 < end; k += 2) {
        int s0 = g_srcs[k], s1 = g_srcs[k + 1];
        float e0 = g_as[s0 * 8 + hidx] + advb;
        float e1 = g_as[s1 * 8 + hidx] + advb;
        float4 h0 = *(const float4*)(g_h + (size_t)s0 * 128 + lane * 4);
        float4 h1 = *(const float4*)(g_h + (size_t)s1 * 128 + lane * 4);
        e0 = e0 > 0.f ? e0 : 0.2f * e0;
        e1 = e1 > 0.f ? e1 : 0.2f * e1;
        float a0 = __expf(e0) * rden;
        float a1 = __expf(e1) * rden;
        acc.x += a0 * h0.x + a1 * h1.x;
        acc.y += a0 * h0.y + a1 * h1.y;
        acc.z += a0 * h0.z + a1 * h1.z;
        acc.w += a0 * h0.w + a1 * h1.w;
    }
    if (k < end) {
        int s0 = g_srcs[k];
        float e0 = g_as[s0 * 8 + hidx] + advb;
        e0 = e0 > 0.f ? e0 : 0.2f * e0;
        float a0 = __expf(e0) * rden;
        float4 h0 = *(const float4*)(g_h + (size_t)s0 * 128 + lane * 4);
        acc.x += a0 * h0.x; acc.y += a0 * h0.y;
        acc.z += a0 * h0.z; acc.w += a0 * h0.w;
    }
    float4 bv = *(const float4*)(bias + lane * 4);
    acc.x += bv.x; acc.y += bv.y; acc.z += bv.z; acc.w += bv.w;
    if (do_elu) {
        acc.x = acc.x > 0.f ? acc.x : __expf(acc.x) - 1.f;
        acc.y = acc.y > 0.f ? acc.y : __expf(acc.y) - 1.f;
        acc.z = acc.z > 0.f ? acc.z : __expf(acc.z) - 1.f;
        acc.w = acc.w > 0.f ? acc.w : __expf(acc.w) - 1.f;
    }
    *(float4*)(g_y + (size_t)gw * 128 + lane * 4) = acc;
}

// ---------------- layer 3 GEMM ([N,128]x[128,6]) + coefficients, warp per node ----------------
__global__ void k_gemm3(const float* __restrict__ W3, const float* __restrict__ attS,
                        const float* __restrict__ attD, int N) {
    __shared__ float w[768];
    for (int i = threadIdx.x; i < 768; i += blockDim.x) w[i] = W3[i];
    __syncthreads();
    int gw = (blockIdx.x * blockDim.x + threadIdx.x) >> 5;
    int lane = threadIdx.x & 31;
    if (gw >= N) return;
    float4 xv = *(const float4*)(g_y + (size_t)gw * 128 + lane * 4);
    int c = lane * 4;
    float p[6];
#pragma unroll
    for (int j = 0; j < 6; j++)
        p[j] = xv.x * w[c * 6 + j] + xv.y * w[(c + 1) * 6 + j] +
               xv.z * w[(c + 2) * 6 + j] + xv.w * w[(c + 3) * 6 + j];
#pragma unroll
    for (int j = 0; j < 6; j++)
#pragma unroll
        for (int o = 16; o > 0; o >>= 1) p[j] += __shfl_xor_sync(0xffffffffu, p[j], o);
    if (lane == 0) {
        float s = 0.f, d = 0.f;
#pragma unroll
        for (int j = 0; j < 6; j++) {
            g_h3[(size_t)gw * 6 + j] = p[j];
            s += p[j] * attS[j];
            d += p[j] * attD[j];
        }
        g_as3[gw] = s;
        g_ad3[gw] = d;
    }
}

// ---------------- layer 3 softmax + aggregation, warp per node (max-free) ----------------
__global__ void k_agg3(const float* __restrict__ b3, float* __restrict__ out, int N) {
    int gw = (blockIdx.x * blockDim.x + threadIdx.x) >> 5;
    int lane = threadIdx.x & 31;
    if (gw >= N) return;
    const int start = g_rowptr[gw], end = g_rowptr[gw + 1];
    const float adv = g_ad3[gw];
    float den = 0.f;
    float acc[6] = {0.f, 0.f, 0.f, 0.f, 0.f, 0.f};
    for (int k = start + lane; k < end; k += 32) {
        int s = g_srcs[k];
        float e = g_as3[s] + adv;
        e = e > 0.f ? e : 0.2f * e;
        float ex = __expf(e);
        den += ex;
#pragma unroll
        for (int j = 0; j < 6; j++) acc[j] += ex * g_h3[(size_t)s * 6 + j];
    }
#pragma unroll
    for (int o = 16; o > 0; o >>= 1) den += __shfl_xor_sync(0xffffffffu, den, o);
#pragma unroll
    for (int j = 0; j < 6; j++)
#pragma unroll
        for (int o = 16; o > 0; o >>= 1) acc[j] += __shfl_xor_sync(0xffffffffu, acc[j], o);
    if (lane == 0) {
        float rden = 1.f / (den + 1e-16f);
#pragma unroll
        for (int j = 0; j < 6; j++) out[(size_t)gw * 6 + j] = acc[j] * rden + b3[j];
    }
}

// ---------------- launch ----------------
extern "C" void kernel_launch(void* const* d_in, const int* in_sizes, int n_in,
                              void* d_out, int out_size) {
    const float* x  = (const float*)d_in[0];
    const void*  ei = d_in[1];
    const float* W1 = (const float*)d_in[2];
    const float* b1 = (const float*)d_in[3];
    const float* s1 = (const float*)d_in[4];
    const float* t1 = (const float*)d_in[5];
    const float* W2 = (const float*)d_in[6];
    const float* b2 = (const float*)d_in[7];
    const float* s2 = (const float*)d_in[8];
    const float* t2 = (const float*)d_in[9];
    const float* W3 = (const float*)d_in[10];
    const float* b3 = (const float*)d_in[11];
    const float* s3 = (const float*)d_in[12];
    const float* t3 = (const float*)d_in[13];
    const int N = in_sizes[0] / 256;
    const int E = in_sizes[1] / 2;
    float* out = (float*)d_out;

    const int eb = (E + 255) / 256;
    const int nb = (N + 255) / 256;
    const int sb = (N + 1023) / 1024;
    const int wb = (N * 32 + 255) / 256;   // warp-per-node grids
    const int gb = (N + 127) / 128;

    // graph preprocessing: dst-CSR with deterministic self-loop slot
    k_detect<<<1, 256>>>((const int*)ei);
    k_initdeg<<<nb, 256>>>(N);
    k_convert_count<<<eb, 256>>>(ei, E);
    k_scan1<<<sb, 1024>>>(N);
    k_scan2<<<1, 128>>>(sb);
    k_scan3<<<sb, 1024>>>(N);
    k_self<<<nb, 256>>>(N);
    k_scatter<<<eb, 256>>>(E);

    // layer 1: x[N,256] @ W1 -> g_h (+coefs); attention -> g_y (ELU)
    k_sgemm<256, false><<<gb, 256>>>(x, W1, N, s1, t1);
    k_agg<<<wb, 256>>>(b1, N, 1);

    // layer 2: g_y @ W2 -> g_h (+coefs); attention -> g_y (ELU)
    k_sgemm<128, true><<<gb, 256>>>(x /*unused*/, W2, N, s2, t2);
    k_agg<<<wb, 256>>>(b2, N, 1);

    // layer 3: g_y @ W3 -> g_h3 (+coefs); attention -> out (+b3)
    k_gemm3<<<wb, 256>>>(W3, s3, t3, N);
    k_agg3<<<wb, 256>>>(b3, out, N);
}

// round 17
// speedup vs baseline: 1.2267x; 1.0129x over previous
#include <cuda_runtime.h>
#include <mma.h>
#include <cstdint>

using namespace nvcuda;

// ---------------- static scratch (no allocations allowed) ----------------
#define N_MAX 100000
#define E_MAX 1600000

// g_h padded by 128 rows: boundary GEMM block stores a full 128-row tile.
__device__ __align__(16) float g_h  [(size_t)(N_MAX + 128) * 128];
__device__ __align__(16) float g_y  [(size_t)N_MAX * 128];
__device__ float g_as [N_MAX * 8];
__device__ float g_ad [N_MAX * 8];
__device__ float g_h3 [N_MAX * 6];
__device__ float g_as3[N_MAX];
__device__ float g_ad3[N_MAX];
__device__ int   g_deg   [N_MAX];
__device__ int   g_incl  [N_MAX];
__device__ int   g_rowptr[N_MAX + 1];
__device__ int   g_wofs  [N_MAX];
__device__ int   g_srcs  [E_MAX + N_MAX];
__device__ int   g_esrc  [E_MAX];
__device__ int   g_edst  [E_MAX];
__device__ int   g_bsums [128];
__device__ int   g_flag;

// ---------------- edge dtype detection ----------------
__global__ void k_detect(const int* __restrict__ ei) {
    __shared__ int any;
    if (threadIdx.x == 0) any = 0;
    __syncthreads();
    for (int i = threadIdx.x; i < 2048; i += blockDim.x)
        if (ei[2 * i + 1] != 0) any = 1;
    __syncthreads();
    if (threadIdx.x == 0) g_flag = (any == 0) ? 1 : 0;
}

__global__ void k_initdeg(int n) {
    int i = blockIdx.x * blockDim.x + threadIdx.x;
    if (i < n) g_deg[i] = 1;
}

__global__ void k_convert_count(const void* __restrict__ ei, int E) {
    int i = blockIdx.x * blockDim.x + threadIdx.x;
    if (i >= E) return;
    int s, d;
    if (g_flag) {
        const long long* p = (const long long*)ei;
        s = (int)p[i];
        d = (int)p[(size_t)E + i];
    } else {
        const int* p = (const int*)ei;
        s = p[i];
        d = p[E + i];
    }
    g_esrc[i] = s;
    g_edst[i] = d;
    atomicAdd(&g_deg[d], 1);
}

// ---------------- CSR-by-dst build ----------------
__global__ void k_scan1(int n) {
    __shared__ int sh[1024];
    int i = blockIdx.x * 1024 + threadIdx.x;
    int v = (i < n) ? g_deg[i] : 0;
    sh[threadIdx.x] = v;
    __syncthreads();
    for (int off = 1; off < 1024; off <<= 1) {
        int t = (threadIdx.x >= off) ? sh[threadIdx.x - off] : 0;
        __syncthreads();
        sh[threadIdx.x] += t;
        __syncthreads();
    }
    if (i < n) g_incl[i] = sh[threadIdx.x];
    if (threadIdx.x == 1023) g_bsums[blockIdx.x] = sh[1023];
}
__global__ void k_scan2(int nb) {
    __shared__ int sh[128];
    int t = threadIdx.x;
    int v = (t < nb) ? g_bsums[t] : 0;
    sh[t] = v;
    __syncthreads();
    for (int off = 1; off < 128; off <<= 1) {
        int u = (t >= off) ? sh[t - off] : 0;
        __syncthreads();
        sh[t] += u;
        __syncthreads();
    }
    if (t < nb) g_bsums[t] = sh[t] - v;
}
__global__ void k_scan3(int n) {
    int i = blockIdx.x * 1024 + threadIdx.x;
    if (i < n) {
        int b = g_bsums[i >> 10];
        g_rowptr[i] = g_incl[i] - g_deg[i] + b;
        if (i == n - 1) g_rowptr[n] = g_incl[i] + b;
    }
}
__global__ void k_self(int n) {
    int i = blockIdx.x * blockDim.x + threadIdx.x;
    if (i < n) {
        int r = g_rowptr[i];
        g_srcs[r] = i;
        g_wofs[i] = r + 1;
    }
}
__global__ void k_scatter(int E) {
    int i = blockIdx.x * blockDim.x + threadIdx.x;
    if (i < E) {
        int d = g_edst[i];
        int pos = atomicAdd(&g_wofs[d], 1);
        g_srcs[pos] = g_esrc[i];
    }
}

// ---------------- tf32 tensor-core GEMM: [M,KDIM] x [KDIM,128] -> g_h ----------------
// Block tile 128x128, 8 warps (4x2), warp tile 32x64 via wmma m16n16k8 tf32.
// Epilogue recomputes per-node attention coefficient dots from the just-stored
// (cache-hot) rows of g_h.
template <int KDIM, bool A_GY>
__global__ __launch_bounds__(256) void k_mm(const float* __restrict__ Aext,
                                            const float* __restrict__ B, int M,
                                            const float* __restrict__ attS,
                                            const float* __restrict__ attD) {
    const float* A = A_GY ? (const float*)g_y : Aext;
    __shared__ float As[128][40];   // 32-wide K chunk + pad (ldm 40, 160B rows)
    __shared__ float Bs[32][136];   // 128-wide N + pad   (ldm 136, 544B rows)
    __shared__ float sS[128], sD[128];

    const int tid = threadIdx.x;
    const int warpId = tid >> 5;
    const int lane = tid & 31;
    const int wm = warpId & 3;      // 4 warp-rows of 32
    const int wn = warpId >> 2;     // 2 warp-cols of 64
    const int rowBase = blockIdx.x * 128;

    if (tid < 128) { sS[tid] = attS[tid]; sD[tid] = attD[tid]; }

    wmma::fragment<wmma::accumulator, 16, 16, 8, float> acc[2][4];
#pragma unroll
    for (int mi = 0; mi < 2; mi++)
#pragma unroll
        for (int ni = 0; ni < 4; ni++) wmma::fill_fragment(acc[mi][ni], 0.0f);

    for (int k0 = 0; k0 < KDIM; k0 += 32) {
        // A tile: 128 rows x 32 cols = 1024 float4-loads by 256 threads
#pragma unroll
        for (int i = 0; i < 4; i++) {
            int idx = tid + i * 256;
            int r = idx >> 3, c4 = idx & 7;
            int row = rowBase + r;
            float4 v = make_float4(0.f, 0.f, 0.f, 0.f);
            if (row < M) v = *(const float4*)(A + (size_t)row * KDIM + k0 + c4 * 4);
            float* dst = &As[r][c4 * 4];
            dst[0] = wmma::__float_to_tf32(v.x);
            dst[1] = wmma::__float_to_tf32(v.y);
            dst[2] = wmma::__float_to_tf32(v.z);
            dst[3] = wmma::__float_to_tf32(v.w);
        }
        // B tile: 32 rows x 128 cols
#pragma unroll
        for (int i = 0; i < 4; i++) {
            int idx = tid + i * 256;
            int kr = idx >> 5, c4 = idx & 31;
            float4 v = *(const float4*)(B + (size_t)(k0 + kr) * 128 + c4 * 4);
            float* dst = &Bs[kr][c4 * 4];
            dst[0] = wmma::__float_to_tf32(v.x);
            dst[1] = wmma::__float_to_tf32(v.y);
            dst[2] = wmma::__float_to_tf32(v.z);
            dst[3] = wmma::__float_to_tf32(v.w);
        }
        __syncthreads();
#pragma unroll
        for (int kk = 0; kk < 4; kk++) {
            wmma::fragment<wmma::matrix_a, 16, 16, 8, wmma::precision::tf32, wmma::row_major> af[2];
            wmma::fragment<wmma::matrix_b, 16, 16, 8, wmma::precision::tf32, wmma::row_major> bf[4];
#pragma unroll
            for (int mi = 0; mi < 2; mi++)
                wmma::load_matrix_sync(af[mi], &As[wm * 32 + mi * 16][kk * 8], 40);
#pragma unroll
            for (int ni = 0; ni < 4; ni++)
                wmma::load_matrix_sync(bf[ni], &Bs[kk * 8][wn * 64 + ni * 16], 136);
#pragma unroll
            for (int mi = 0; mi < 2; mi++)
#pragma unroll
                for (int ni = 0; ni < 4; ni++)
                    wmma::mma_sync(acc[mi][ni], af[mi], bf[ni], acc[mi][ni]);
        }
        __syncthreads();
    }

    // store accumulators straight to g_h (row-major, padded rows beyond M are scratch)
#pragma unroll
    for (int mi = 0; mi < 2; mi++)
#pragma unroll
        for (int ni = 0; ni < 4; ni++)
            wmma::store_matrix_sync(
                g_h + (size_t)(rowBase + wm * 32 + mi * 16) * 128 + wn * 64 + ni * 16,
                acc[mi][ni], 128, wmma::mem_row_major);
    __syncthreads();   // make block's global stores visible block-wide

    // fused attention coefficients: warp per row, 16 rows per warp (cache-hot reads)
    for (int it = 0; it < 16; it++) {
        int row = rowBase + warpId * 16 + it;
        if (row >= M) break;
        float4 hv = *(const float4*)(g_h + (size_t)row * 128 + lane * 4);
        float4 sv = *(const float4*)(&sS[lane * 4]);
        float4 dv = *(const float4*)(&sD[lane * 4]);
        float ps = hv.x * sv.x + hv.y * sv.y + hv.z * sv.z + hv.w * sv.w;
        float pd = hv.x * dv.x + hv.y * dv.y + hv.z * dv.z + hv.w * dv.w;
        ps += __shfl_xor_sync(0xffffffffu, ps, 1);
        ps += __shfl_xor_sync(0xffffffffu, ps, 2);
        pd += __shfl_xor_sync(0xffffffffu, pd, 1);
        pd += __shfl_xor_sync(0xffffffffu, pd, 2);
        if ((lane & 3) == 0) {
            g_as[row * 8 + (lane >> 2)] = ps;
            g_ad[row * 8 + (lane >> 2)] = pd;
        }
    }
}

// ---------------- softmax + aggregation (layers 1,2): warp per node ----------------
__global__ void k_agg(const float* __restrict__ bias, int N, int do_elu) {
    int gw = (blockIdx.x * blockDim.x + threadIdx.x) >> 5;
    int lane = threadIdx.x & 31;
    if (gw >= N) return;
    const int start = g_rowptr[gw], end = g_rowptr[gw + 1];

    const int h8 = lane & 7;
    const float adv = g_ad[gw * 8 + h8];
    float den = 0.f;
    for (int k = start + (lane >> 3); k < end; k += 4) {
        int s = g_srcs[k];
        float e = g_as[s * 8 + h8] + adv;
        e = e > 0.f ? e : 0.2f * e;
        den += __expf(e);
    }
    den += __shfl_xor_sync(0xffffffffu, den, 8);
    den += __shfl_xor_sync(0xffffffffu, den, 16);

    const int hidx = lane >> 2;
    float rden = 1.f / (__shfl_sync(0xffffffffu, den, hidx) + 1e-16f);
    float advb = __shfl_sync(0xffffffffu, adv, hidx);

    float4 acc = make_float4(0.f, 0.f, 0.f, 0.f);
    int k = start;
    for (; k + 1 < end; k += 2) {
        int s0 = g_srcs[k], s1 = g_srcs[k + 1];
        float e0 = g_as[s0 * 8 + hidx] + advb;
        float e1 = g_as[s1 * 8 + hidx] + advb;
        float4 h0 = *(const float4*)(g_h + (size_t)s0 * 128 + lane * 4);
        float4 h1 = *(const float4*)(g_h + (size_t)s1 * 128 + lane * 4);
        e0 = e0 > 0.f ? e0 : 0.2f * e0;
        e1 = e1 > 0.f ? e1 : 0.2f * e1;
        float a0 = __expf(e0) * rden;
        float a1 = __expf(e1) * rden;
        acc.x += a0 * h0.x + a1 * h1.x;
        acc.y += a0 * h0.y + a1 * h1.y;
        acc.z += a0 * h0.z + a1 * h1.z;
        acc.w += a0 * h0.w + a1 * h1.w;
    }
    if (k < end) {
        int s0 = g_srcs[k];
        float e0 = g_as[s0 * 8 + hidx] + advb;
        e0 = e0 > 0.f ? e0 : 0.2f * e0;
        float a0 = __expf(e0) * rden;
        float4 h0 = *(const float4*)(g_h + (size_t)s0 * 128 + lane * 4);
        acc.x += a0 * h0.x; acc.y += a0 * h0.y;
        acc.z += a0 * h0.z; acc.w += a0 * h0.w;
    }
    float4 bv = *(const float4*)(bias + lane * 4);
    acc.x += bv.x; acc.y += bv.y; acc.z += bv.z; acc.w += bv.w;
    if (do_elu) {
        acc.x = acc.x > 0.f ? acc.x : __expf(acc.x) - 1.f;
        acc.y = acc.y > 0.f ? acc.y : __expf(acc.y) - 1.f;
        acc.z = acc.z > 0.f ? acc.z : __expf(acc.z) - 1.f;
        acc.w = acc.w > 0.f ? acc.w : __expf(acc.w) - 1.f;
    }
    *(float4*)(g_y + (size_t)gw * 128 + lane * 4) = acc;
}

// ---------------- layer 3 GEMM ([N,128]x[128,6]) + coefficients ----------------
__global__ void k_gemm3(const float* __restrict__ W3, const float* __restrict__ attS,
                        const float* __restrict__ attD, int N) {
    __shared__ float w[768];
    for (int i = threadIdx.x; i < 768; i += blockDim.x) w[i] = W3[i];
    __syncthreads();
    int gw = (blockIdx.x * blockDim.x + threadIdx.x) >> 5;
    int lane = threadIdx.x & 31;
    if (gw >= N) return;
    float4 xv = *(const float4*)(g_y + (size_t)gw * 128 + lane * 4);
    int c = lane * 4;
    float p[6];
#pragma unroll
    for (int j = 0; j < 6; j++)
        p[j] = xv.x * w[c * 6 + j] + xv.y * w[(c + 1) * 6 + j] +
               xv.z * w[(c + 2) * 6 + j] + xv.w * w[(c + 3) * 6 + j];
#pragma unroll
    for (int j = 0; j < 6; j++)
#pragma unroll
        for (int o = 16; o > 0; o >>= 1) p[j] += __shfl_xor_sync(0xffffffffu, p[j], o);
    if (lane == 0) {
        float s = 0.f, d = 0.f;
#pragma unroll
        for (int j = 0; j < 6; j++) {
            g_h3[(size_t)gw * 6 + j] = p[j];
            s += p[j] * attS[j];
            d += p[j] * attD[j];
        }
        g_as3[gw] = s;
        g_ad3[gw] = d;
    }
}

// ---------------- layer 3 softmax + aggregation (max-free, single pass) ----------------
__global__ void k_agg3(const float* __restrict__ b3, float* __restrict__ out, int N) {
    int gw = (blockIdx.x * blockDim.x + threadIdx.x) >> 5;
    int lane = threadIdx.x & 31;
    if (gw >= N) return;
    const int start = g_rowptr[gw], end = g_rowptr[gw + 1];
    const float adv = g_ad3[gw];
    float den = 0.f;
    float acc[6] = {0.f, 0.f, 0.f, 0.f, 0.f, 0.f};
    for (int k = start + lane; k < end; k += 32) {
        int s = g_srcs[k];
        float e = g_as3[s] + adv;
        e = e > 0.f ? e : 0.2f * e;
        float ex = __expf(e);
        den += ex;
#pragma unroll
        for (int j = 0; j < 6; j++) acc[j] += ex * g_h3[(size_t)s * 6 + j];
    }
#pragma unroll
    for (int o = 16; o > 0; o >>= 1) den += __shfl_xor_sync(0xffffffffu, den, o);
#pragma unroll
    for (int j = 0; j < 6; j++)
#pragma unroll
        for (int o = 16; o > 0; o >>= 1) acc[j] += __shfl_xor_sync(0xffffffffu, acc[j], o);
    if (lane == 0) {
        float rden = 1.f / (den + 1e-16f);
#pragma unroll
        for (int j = 0; j < 6; j++) out[(size_t)gw * 6 + j] = acc[j] * rden + b3[j];
    }
}

// ---------------- launch ----------------
extern "C" void kernel_launch(void* const* d_in, const int* in_sizes, int n_in,
                              void* d_out, int out_size) {
    const float* x  = (const float*)d_in[0];
    const void*  ei = d_in[1];
    const float* W1 = (const float*)d_in[2];
    const float* b1 = (const float*)d_in[3];
    const float* s1 = (const float*)d_in[4];
    const float* t1 = (const float*)d_in[5];
    const float* W2 = (const float*)d_in[6];
    const float* b2 = (const float*)d_in[7];
    const float* s2 = (const float*)d_in[8];
    const float* t2 = (const float*)d_in[9];
    const float* W3 = (const float*)d_in[10];
    const float* b3 = (const float*)d_in[11];
    const float* s3 = (const float*)d_in[12];
    const float* t3 = (const float*)d_in[13];
    const int N = in_sizes[0] / 256;
    const int E = in_sizes[1] / 2;
    float* out = (float*)d_out;

    const int eb = (E + 255) / 256;
    const int nb = (N + 255) / 256;
    const int sb = (N + 1023) / 1024;
    const int wb = (N * 32 + 255) / 256;
    const int gb = (N + 127) / 128;

    // graph preprocessing: dst-CSR with deterministic self-loop slot
    k_detect<<<1, 256>>>((const int*)ei);
    k_initdeg<<<nb, 256>>>(N);
    k_convert_count<<<eb, 256>>>(ei, E);
    k_scan1<<<sb, 1024>>>(N);
    k_scan2<<<1, 128>>>(sb);
    k_scan3<<<sb, 1024>>>(N);
    k_self<<<nb, 256>>>(N);
    k_scatter<<<eb, 256>>>(E);

    // layer 1: x[N,256] @ W1 -> g_h (tf32 MMA, +coefs); attention -> g_y (ELU)
    k_mm<256, false><<<gb, 256>>>(x, W1, N, s1, t1);
    k_agg<<<wb, 256>>>(b1, N, 1);

    // layer 2: g_y @ W2 -> g_h (tf32 MMA, +coefs); attention -> g_y (ELU)
    k_mm<128, true><<<gb, 256>>>(x /*unused*/, W2, N, s2, t2);
    k_agg<<<wb, 256>>>(b2, N, 1);

    // layer 3: g_y @ W3 -> g_h3 (+coefs); attention -> out (+b3)
    k_gemm3<<<wb, 256>>>(W3, s3, t3, N);
    k_agg3<<<wb, 256>>>(b3, out, N);
}